// round 3
// baseline (speedup 1.0000x reference)
#include <cuda_runtime.h>

#define BB   64
#define EMBD 256
#define HIDD 512
#define VOC  32000
#define TT   64

typedef unsigned long long ull;

// ---------------- scratch (device globals; no allocation) ----------------
__device__ float g_hbuf[2][BB * HIDD];
__device__ float g_cbuf[BB * HIDD];
__device__ ull   g_amax[TT][BB];
__device__ int   g_tmode[1];   // 1 => target stored as int64, 0 => int32

// ---------------- helpers ----------------
__device__ __forceinline__ ull ffma2(ull a, ull b, ull c) {
    ull d;
    asm("fma.rn.f32x2 %0, %1, %2, %3;" : "=l"(d) : "l"(a), "l"(b), "l"(c));
    return d;
}

// accurate sigmoid/tanh, immune to fast-math approx substitution
__device__ __forceinline__ float sigm_acc(float x) {
    // 1/(1+e^{-x}) = 1/(2 + expm1(-x)) ; expm1 overflow -> +inf -> 0 (correct limit)
    return 1.0f / (2.0f + expm1f(-x));
}
__device__ __forceinline__ float tanh_acc(float x) {
    float ax = fabsf(x);
    if (ax > 9.0f) return copysignf(1.0f, x);
    float e = expm1f(2.0f * ax);
    return copysignf(e / (e + 2.0f), x);
}

__device__ __forceinline__ ull pack_key(float v, int n) {
    unsigned u = __float_as_uint(v);
    u = (u & 0x80000000u) ? ~u : (u | 0x80000000u);      // monotonic float->uint
    return ((ull)u << 32) | (ull)(0xFFFFFFFFu - (unsigned)n); // ties -> smaller n wins
}

// ---------------- init: copy h/c, zero argmax scratch, detect target dtype ----
__global__ void init_kernel(const float* __restrict__ eh, const float* __restrict__ ec,
                            const int* __restrict__ tgt_i32) {
    int idx = blockIdx.x * blockDim.x + threadIdx.x;
    if (idx < BB * HIDD) {
        g_hbuf[0][idx] = eh[idx];
        g_cbuf[idx]    = ec[idx];
    }
    if (idx < TT * BB) ((ull*)g_amax)[idx] = 0ull;
    if (idx == 0) {
        // int64 little-endian: odd int32 words are high halves == 0
        g_tmode[0] = ((tgt_i32[1] | tgt_i32[3] | tgt_i32[5] | tgt_i32[7]) == 0) ? 1 : 0;
    }
}

// ---------------- gates + LSTM pointwise (fused) ----------------
// grid 128 (hidden chunk of 4), block 256.
// Thread (n16 = tid&15, mg = tid>>4): owns gate-row r = (n16>>2)*512 + j0 + (n16&3)
// for 4 batch rows m = mg*4 + i. Full K accumulated per thread (f32x2 k-pairs).
__global__ void __launch_bounds__(256)
gates_kernel(int t,
             const long long* __restrict__ tgt64, const int* __restrict__ tgt32,
             const int* __restrict__ tf_mask,
             const float* __restrict__ emb,
             const float* __restrict__ w_ih, const float* __restrict__ w_hh,
             const float* __restrict__ b_ih, const float* __restrict__ b_hh) {
    __shared__ float s_xh[BB][64];      // [m][k-chunk]
    __shared__ float s_w[16][66];       // 16 gate-rows x 64 k (pad 66 for banks)
    __shared__ float s_gate[16][BB];    // [g*4+jj][m]
    __shared__ int   s_inp[BB];

    const int tid = threadIdx.x;
    const int j0  = blockIdx.x * 4;

    if (tid < BB) {
        int inp = 0;
        if (t > 0) {
            if (tf_mask[t - 1] > 0) {
                inp = g_tmode[0] ? (int)tgt64[(size_t)tid * TT + (t - 1)]
                                 : tgt32[(size_t)tid * TT + (t - 1)];
            } else {
                ull p = g_amax[t - 1][tid];
                inp = (int)(0xFFFFFFFFu - (unsigned)(p & 0xFFFFFFFFull));
            }
        }
        s_inp[tid] = inp;
    }
    __syncthreads();

    const int n16 = tid & 15;
    const int mg  = tid >> 4;                 // 0..15, m = mg*4+i
    const int r   = (n16 >> 2) * HIDD + j0 + (n16 & 3);
    const float* __restrict__ hprev = g_hbuf[t & 1];

    ull acc[4] = {0ull, 0ull, 0ull, 0ull};

    // ---- phase 1: x = embedding[inp], K = 256 ----
    for (int kc = 0; kc < EMBD; kc += 64) {
        __syncthreads();
#pragma unroll
        for (int it = 0; it < 16; ++it) {
            int idx = tid + it * 256;          // 0..4095
            int m = idx >> 6, k = idx & 63;
            s_xh[m][k] = emb[(size_t)s_inp[m] * EMBD + kc + k];
        }
#pragma unroll
        for (int it = 0; it < 4; ++it) {
            int idx = tid + it * 256;          // 0..1023
            int rr = idx >> 6, k = idx & 63;
            int row = (rr >> 2) * HIDD + j0 + (rr & 3);
            s_w[rr][k] = w_ih[(size_t)row * EMBD + kc + k];
        }
        __syncthreads();
#pragma unroll
        for (int kk = 0; kk < 64; kk += 2) {
            ull w2 = *(const ull*)&s_w[n16][kk];
#pragma unroll
            for (int i = 0; i < 4; ++i)
                acc[i] = ffma2(w2, *(const ull*)&s_xh[mg * 4 + i][kk], acc[i]);
        }
    }

    // ---- phase 2: h_prev, K = 512 ----
    for (int kc = 0; kc < HIDD; kc += 64) {
        __syncthreads();
#pragma unroll
        for (int it = 0; it < 16; ++it) {
            int idx = tid + it * 256;
            int m = idx >> 6, k = idx & 63;
            s_xh[m][k] = hprev[(size_t)m * HIDD + kc + k];
        }
#pragma unroll
        for (int it = 0; it < 4; ++it) {
            int idx = tid + it * 256;
            int rr = idx >> 6, k = idx & 63;
            int row = (rr >> 2) * HIDD + j0 + (rr & 3);
            s_w[rr][k] = w_hh[(size_t)row * HIDD + kc + k];
        }
        __syncthreads();
#pragma unroll
        for (int kk = 0; kk < 64; kk += 2) {
            ull w2 = *(const ull*)&s_w[n16][kk];
#pragma unroll
            for (int i = 0; i < 4; ++i)
                acc[i] = ffma2(w2, *(const ull*)&s_xh[mg * 4 + i][kk], acc[i]);
        }
    }

    // ---- finalize gates into smem ----
    {
        float bias = b_ih[r] + b_hh[r];
#pragma unroll
        for (int i = 0; i < 4; ++i) {
            float2 p = *(float2*)&acc[i];
            s_gate[n16][mg * 4 + i] = p.x + p.y + bias;
        }
    }
    __syncthreads();

    // ---- LSTM pointwise: 256 threads = 64 m x 4 jj ----
    {
        int m  = tid & 63;
        int jj = tid >> 6;
        float iv = sigm_acc(s_gate[jj][m]);
        float fv = sigm_acc(s_gate[4 + jj][m]);
        float gv = tanh_acc(s_gate[8 + jj][m]);
        float ov = sigm_acc(s_gate[12 + jj][m]);
        int j = j0 + jj;
        float c0 = g_cbuf[(size_t)m * HIDD + j];
        float c1 = fv * c0 + iv * gv;
        float h1 = ov * tanh_acc(c1);
        g_cbuf[(size_t)m * HIDD + j]            = c1;
        g_hbuf[(t + 1) & 1][(size_t)m * HIDD + j] = h1;
    }
}

// ---------------- fc + fused argmax ----------------
// grid 296 = (m-half) x (148 n-ranges of 216/217), block 256.
// Thread (nth = tid&31, mg = tid>>5): tile 4m x 8n, f32x2 along k.
__global__ void __launch_bounds__(256)
fc_kernel(int t, const float* __restrict__ fc_w, const float* __restrict__ fc_b,
          float* __restrict__ out) {
    __shared__ float s_h[32][32];        // [m_local][k-chunk]
    __shared__ float s_w[256][34];       // [n_local][k-chunk], pad 34 (8B-aligned rows)
    __shared__ ull   s_amax[32];

    const int tid = threadIdx.x;
    const int bm  = blockIdx.x & 1;
    const int nb  = blockIdx.x >> 1;                   // 0..147
    const int m0  = bm * 32;
    const int nbase = nb * 216 + (nb < 32 ? nb : 32);
    const int ncnt  = 216 + (nb < 32 ? 1 : 0);

    const int nth = tid & 31;
    const int mg  = tid >> 5;                          // 0..7 (warp-uniform)
    const float* __restrict__ hsrc = g_hbuf[(t + 1) & 1];

    if (tid < 32) s_amax[tid] = 0ull;

    ull acc[4][8];
#pragma unroll
    for (int i = 0; i < 4; ++i)
#pragma unroll
        for (int j = 0; j < 8; ++j) acc[i][j] = 0ull;

    for (int kc = 0; kc < HIDD; kc += 32) {
        __syncthreads();
        // stage h tile: 32m x 32k, one float4 per thread
        {
            int m = tid >> 3, kq = tid & 7;
            *(float4*)&s_h[m][kq * 4] =
                *(const float4*)&hsrc[(size_t)(m0 + m) * HIDD + kc + kq * 4];
        }
        // stage w tile: 256n x 32k as float2 (16 per thread)
#pragma unroll
        for (int it = 0; it < 16; ++it) {
            int idx = tid + it * 256;                  // 0..4095
            int nl = idx >> 4, kq = idx & 15;          // kq: float2 index
            float2 v = make_float2(0.f, 0.f);
            if (nl < ncnt)
                v = *(const float2*)&fc_w[(size_t)(nbase + nl) * HIDD + kc + kq * 2];
            *(float2*)&s_w[nl][kq * 2] = v;
        }
        __syncthreads();
#pragma unroll
        for (int kk = 0; kk < 32; kk += 2) {
            ull x2[4];
#pragma unroll
            for (int i = 0; i < 4; ++i)
                x2[i] = *(const ull*)&s_h[mg * 4 + i][kk];   // warp-broadcast
#pragma unroll
            for (int j = 0; j < 8; ++j) {
                ull w2 = *(const ull*)&s_w[nth + 32 * j][kk];
#pragma unroll
                for (int i = 0; i < 4; ++i)
                    acc[i][j] = ffma2(x2[i], w2, acc[i][j]);
            }
        }
    }

    // epilogue: bias, store, argmax
    ull best[4] = {0ull, 0ull, 0ull, 0ull};
#pragma unroll
    for (int j = 0; j < 8; ++j) {
        int nl = nth + 32 * j;
        bool ok = nl < ncnt;
        int n = nbase + nl;
        float fb = ok ? fc_b[n] : 0.f;
#pragma unroll
        for (int i = 0; i < 4; ++i) {
            float2 p = *(float2*)&acc[i][j];
            float v = p.x + p.y + fb;
            if (ok) {
                int m = m0 + mg * 4 + i;
                out[((size_t)m * TT + t) * VOC + n] = v;
                ull key = pack_key(v, n);
                if (key > best[i]) best[i] = key;
            }
        }
    }
#pragma unroll
    for (int i = 0; i < 4; ++i) atomicMax(&s_amax[mg * 4 + i], best[i]);
    __syncthreads();
    if (tid < 32) atomicMax(&g_amax[t][m0 + tid], s_amax[tid]);
}

// ---------------- final h/c tail (only if output is concatenated tuple) -------
__global__ void final_kernel(float* __restrict__ out, int out_size) {
    int idx = blockIdx.x * blockDim.x + threadIdx.x;
    const size_t base = (size_t)BB * TT * VOC;
    if ((size_t)out_size >= base + 2ull * BB * HIDD) {
        if (idx < BB * HIDD) {
            out[base + idx]             = g_hbuf[0][idx];   // h after 64 steps is buf 0
            out[base + BB * HIDD + idx] = g_cbuf[idx];
        }
    }
}

// ---------------- launch ----------------
extern "C" void kernel_launch(void* const* d_in, const int* in_sizes, int n_in,
                              void* d_out, int out_size) {
    const float* encoder_h = (const float*)d_in[0];
    const float* encoder_c = (const float*)d_in[1];
    const void*  target    = d_in[2];
    const int*   tf_mask   = (const int*)d_in[3];
    const float* embedding = (const float*)d_in[4];
    const float* w_ih      = (const float*)d_in[5];
    const float* w_hh      = (const float*)d_in[6];
    const float* b_ih      = (const float*)d_in[7];
    const float* b_hh      = (const float*)d_in[8];
    const float* fc_w      = (const float*)d_in[9];
    const float* fc_b      = (const float*)d_in[10];
    float* out = (float*)d_out;

    init_kernel<<<128, 256>>>(encoder_h, encoder_c, (const int*)target);
    for (int t = 0; t < TT; ++t) {
        gates_kernel<<<128, 256>>>(t, (const long long*)target, (const int*)target,
                                   tf_mask, embedding, w_ih, w_hh, b_ih, b_hh);
        fc_kernel<<<296, 256>>>(t, fc_w, fc_b, out);
    }
    final_kernel<<<128, 256>>>(out, out_size);
}

// round 4
// speedup vs baseline: 1.9607x; 1.9607x over previous
#include <cuda_runtime.h>

#define BB   64
#define EMBD 256
#define HIDD 512
#define VOC  32000
#define TT   64

typedef unsigned long long ull;

// ---------------- scratch (device globals; no allocation) ----------------
__device__ __align__(16) float g_hbuf[2][BB * HIDD];
__device__ __align__(16) float g_cbuf[BB * HIDD];
__device__ ull   g_amax[TT][BB];
__device__ int   g_tmode[1];   // 1 => target stored as int64, 0 => int32

// ---------------- helpers ----------------
__device__ __forceinline__ ull ffma2(ull a, ull b, ull c) {
    ull d;
    asm("fma.rn.f32x2 %0, %1, %2, %3;" : "=l"(d) : "l"(a), "l"(b), "l"(c));
    return d;
}

// accurate sigmoid/tanh, immune to fast-math approx substitution
__device__ __forceinline__ float sigm_acc(float x) {
    return 1.0f / (2.0f + expm1f(-x));
}
__device__ __forceinline__ float tanh_acc(float x) {
    float ax = fabsf(x);
    if (ax > 9.0f) return copysignf(1.0f, x);
    float e = expm1f(2.0f * ax);
    return copysignf(e / (e + 2.0f), x);
}

__device__ __forceinline__ ull pack_key(float v, int n) {
    unsigned u = __float_as_uint(v);
    u = (u & 0x80000000u) ? ~u : (u | 0x80000000u);          // monotonic float->uint
    return ((ull)u << 32) | (ull)(0xFFFFFFFFu - (unsigned)n); // ties -> smaller n wins
}

// ---------------- init ----------------
__global__ void init_kernel(const float* __restrict__ eh, const float* __restrict__ ec,
                            const int* __restrict__ tgt_i32) {
    int idx = blockIdx.x * blockDim.x + threadIdx.x;
    if (idx < BB * HIDD) {
        g_hbuf[0][idx] = eh[idx];
        g_cbuf[idx]    = ec[idx];
    }
    if (idx < TT * BB) ((ull*)g_amax)[idx] = 0ull;
    if (idx == 0) {
        g_tmode[0] = ((tgt_i32[1] | tgt_i32[3] | tgt_i32[5] | tgt_i32[7]) == 0) ? 1 : 0;
    }
}

// ---------------- gates + LSTM pointwise (fused, warp split-K) ----------------
// grid 128 (4 hidden cols each -> 16 gate-rows), block 256 = 8 warps.
// Warp w owns K-slice: x-phase k in [w*32,w*32+32), h-phase k in [w*64,w*64+64).
// Lane (mg=lane>>2, rq=lane&3): tile 8m x 4r. XOR-swizzled smem, LDS.128, f32x2.
// Dynamic smem layout (bytes):
//   0      : s_hx   max 64*512 f = 131072
//   131072 : s_w    max 16*512 f = 32768
//   163840 : s_part float[8][16][65] = 33280
//   197120 : s_inp  int[64]
#define G_SMEM_BYTES (197120 + 256)

__global__ void __launch_bounds__(256)
gates_kernel(int t,
             const long long* __restrict__ tgt64, const int* __restrict__ tgt32,
             const int* __restrict__ tf_mask,
             const float* __restrict__ emb,
             const float* __restrict__ w_ih, const float* __restrict__ w_hh,
             const float* __restrict__ b_ih, const float* __restrict__ b_hh) {
    extern __shared__ char smem[];
    ulonglong2* s_hx = (ulonglong2*)smem;                 // quad (16B) units
    ulonglong2* s_w  = (ulonglong2*)(smem + 131072);
    float (*s_part)[16][65] = (float (*)[16][65])(smem + 163840);
    int* s_inp = (int*)(smem + 197120);

    const int tid  = threadIdx.x;
    const int j0   = blockIdx.x * 4;
    const int w    = tid >> 5;
    const int lane = tid & 31;
    const int mg   = lane >> 2;      // 8 m-groups of 8
    const int rq   = lane & 3;       // 4 r-groups of 4 (rq == gate index)

    // ---- token select ----
    if (tid < BB) {
        int inp = 0;
        if (t > 0) {
            if (tf_mask[t - 1] > 0) {
                inp = g_tmode[0] ? (int)tgt64[(size_t)tid * TT + (t - 1)]
                                 : tgt32[(size_t)tid * TT + (t - 1)];
            } else {
                ull p = g_amax[t - 1][tid];
                inp = (int)(0xFFFFFFFFu - (unsigned)(p & 0xFFFFFFFFull));
            }
        }
        s_inp[tid] = inp;
    }
    __syncthreads();

    ull acc[8][4];
#pragma unroll
    for (int i = 0; i < 8; ++i)
#pragma unroll
        for (int j = 0; j < 4; ++j) acc[i][j] = 0ull;

    // ================= phase 1: x = embedding[inp], K = 256 (64 quads) ========
#pragma unroll
    for (int it = 0; it < 16; ++it) {
        int idx = tid + it * 256;                  // 0..4095 float4
        int m = idx >> 6, kq = idx & 63;
        float4 v = *(const float4*)&emb[(size_t)s_inp[m] * EMBD + kq * 4];
        s_hx[m * 64 + (kq ^ (m >> 3))] = *(ulonglong2*)&v;
    }
#pragma unroll
    for (int it = 0; it < 4; ++it) {
        int idx = tid + it * 256;                  // 0..1023 float4
        int rr = idx >> 6, kq = idx & 63;
        int R  = (rr >> 2) * HIDD + j0 + (rr & 3);
        float4 v = *(const float4*)&w_ih[(size_t)R * EMBD + kq * 4];
        s_w[rr * 64 + (kq ^ (rr >> 2))] = *(ulonglong2*)&v;
    }
    __syncthreads();
#pragma unroll
    for (int q8 = 0; q8 < 8; ++q8) {
        int q = w * 8 + q8;
        ulonglong2 xv[8], wv[4];
#pragma unroll
        for (int i = 0; i < 8; ++i) xv[i] = s_hx[(mg * 8 + i) * 64 + (q ^ mg)];
#pragma unroll
        for (int j = 0; j < 4; ++j) wv[j] = s_w[(rq * 4 + j) * 64 + (q ^ rq)];
#pragma unroll
        for (int i = 0; i < 8; ++i)
#pragma unroll
            for (int j = 0; j < 4; ++j) {
                acc[i][j] = ffma2(xv[i].x, wv[j].x, acc[i][j]);
                acc[i][j] = ffma2(xv[i].y, wv[j].y, acc[i][j]);
            }
    }
    __syncthreads();

    // ================= phase 2: h_prev, K = 512 (128 quads) ===================
    const float* __restrict__ hprev = g_hbuf[t & 1];
#pragma unroll
    for (int it = 0; it < 32; ++it) {
        int idx = tid + it * 256;                  // 0..8191 float4
        int m = idx >> 7, kq = idx & 127;
        float4 v = *(const float4*)&hprev[(size_t)m * HIDD + kq * 4];
        s_hx[m * 128 + (kq ^ (m >> 3))] = *(ulonglong2*)&v;
    }
#pragma unroll
    for (int it = 0; it < 8; ++it) {
        int idx = tid + it * 256;                  // 0..2047 float4
        int rr = idx >> 7, kq = idx & 127;
        int R  = (rr >> 2) * HIDD + j0 + (rr & 3);
        float4 v = *(const float4*)&w_hh[(size_t)R * HIDD + kq * 4];
        s_w[rr * 128 + (kq ^ (rr >> 2))] = *(ulonglong2*)&v;
    }
    __syncthreads();
#pragma unroll
    for (int q16 = 0; q16 < 16; ++q16) {
        int q = w * 16 + q16;
        ulonglong2 xv[8], wv[4];
#pragma unroll
        for (int i = 0; i < 8; ++i) xv[i] = s_hx[(mg * 8 + i) * 128 + (q ^ mg)];
#pragma unroll
        for (int j = 0; j < 4; ++j) wv[j] = s_w[(rq * 4 + j) * 128 + (q ^ rq)];
#pragma unroll
        for (int i = 0; i < 8; ++i)
#pragma unroll
            for (int j = 0; j < 4; ++j) {
                acc[i][j] = ffma2(xv[i].x, wv[j].x, acc[i][j]);
                acc[i][j] = ffma2(xv[i].y, wv[j].y, acc[i][j]);
            }
    }

    // ---- write per-warp partials ----
#pragma unroll
    for (int i = 0; i < 8; ++i)
#pragma unroll
        for (int j = 0; j < 4; ++j) {
            float2 p = *(float2*)&acc[i][j];
            s_part[w][rq * 4 + j][mg * 8 + i] = p.x + p.y;
        }
    __syncthreads();

    // ---- reduce 8 warps + LSTM pointwise: thread = (m = tid&63, jj = tid>>6) --
    {
        int m  = tid & 63;
        int jj = tid >> 6;
        float gv4[4];
#pragma unroll
        for (int g = 0; g < 4; ++g) {
            float s = 0.f;
#pragma unroll
            for (int w8 = 0; w8 < 8; ++w8) s += s_part[w8][g * 4 + jj][m];
            int R = g * HIDD + j0 + jj;
            gv4[g] = s + b_ih[R] + b_hh[R];
        }
        float iv = sigm_acc(gv4[0]);
        float fv = sigm_acc(gv4[1]);
        float gg = tanh_acc(gv4[2]);
        float ov = sigm_acc(gv4[3]);
        int j = j0 + jj;
        float c0 = g_cbuf[(size_t)m * HIDD + j];
        float c1 = fv * c0 + iv * gg;
        float h1 = ov * tanh_acc(c1);
        g_cbuf[(size_t)m * HIDD + j]              = c1;
        g_hbuf[(t + 1) & 1][(size_t)m * HIDD + j] = h1;
    }
}

// ---------------- fc + fused argmax ----------------
// grid 250 (n-tile 128), block 256 = 8 warps: (wm = w>>2: 2 m-halves, wn = w&3: 4 n-qtrs).
// Lane (mg=lane>>2, nq=lane&3): tile 4m x 8n. LDS.128 + XOR swizzle, f32x2.
__global__ void __launch_bounds__(256, 2)
fc_kernel(int t, const float* __restrict__ fc_w, const float* __restrict__ fc_b,
          float* __restrict__ out) {
    __shared__ ulonglong2 s_h[64 * 8];       // [m][8 quads]
    __shared__ ulonglong2 s_w[128 * 8];      // [n][8 quads]
    __shared__ float s_b[128];
    __shared__ ull   s_amax[64];

    const int tid  = threadIdx.x;
    const int nb   = blockIdx.x;             // 0..249
    const int w    = tid >> 5;
    const int lane = tid & 31;
    const int wm   = w >> 2;
    const int wn   = w & 3;
    const int mg   = lane >> 2;
    const int nq   = lane & 3;
    const float* __restrict__ hsrc = g_hbuf[(t + 1) & 1];

    if (tid < 64)  s_amax[tid] = 0ull;
    if (tid < 128) s_b[tid]    = fc_b[nb * 128 + tid];

    ull acc[4][8];
#pragma unroll
    for (int i = 0; i < 4; ++i)
#pragma unroll
        for (int j = 0; j < 8; ++j) acc[i][j] = 0ull;

    for (int kc = 0; kc < HIDD; kc += 32) {
        __syncthreads();
#pragma unroll
        for (int it = 0; it < 2; ++it) {
            int idx = tid + it * 256;              // 0..511 float4
            int m = idx >> 3, kq = idx & 7;
            float4 v = *(const float4*)&hsrc[(size_t)m * HIDD + kc + kq * 4];
            s_h[m * 8 + (kq ^ ((m >> 2) & 7))] = *(ulonglong2*)&v;
        }
#pragma unroll
        for (int it = 0; it < 4; ++it) {
            int idx = tid + it * 256;              // 0..1023 float4
            int nl = idx >> 3, kq = idx & 7;
            float4 v = *(const float4*)&fc_w[(size_t)(nb * 128 + nl) * HIDD + kc + kq * 4];
            s_w[nl * 8 + (kq ^ ((nl >> 3) & 3))] = *(ulonglong2*)&v;
        }
        __syncthreads();
#pragma unroll
        for (int q = 0; q < 8; ++q) {
            ulonglong2 xv[4];
#pragma unroll
            for (int i = 0; i < 4; ++i)
                xv[i] = s_h[(wm * 32 + mg * 4 + i) * 8 + (q ^ mg)];
#pragma unroll
            for (int j = 0; j < 8; ++j) {
                ulonglong2 wv = s_w[(wn * 32 + nq * 8 + j) * 8 + (q ^ nq)];
#pragma unroll
                for (int i = 0; i < 4; ++i) {
                    acc[i][j] = ffma2(xv[i].x, wv.x, acc[i][j]);
                    acc[i][j] = ffma2(xv[i].y, wv.y, acc[i][j]);
                }
            }
        }
    }

    // ---- epilogue: bias, store (float4 x2), fused argmax ----
    const int n0l = wn * 32 + nq * 8;
#pragma unroll
    for (int i = 0; i < 4; ++i) {
        int m = wm * 32 + mg * 4 + i;
        ull best = 0ull;
        float v[8];
#pragma unroll
        for (int j = 0; j < 8; ++j) {
            float2 p = *(float2*)&acc[i][j];
            v[j] = p.x + p.y + s_b[n0l + j];
            ull key = pack_key(v[j], nb * 128 + n0l + j);
            if (key > best) best = key;
        }
        float4* dst = (float4*)&out[((size_t)m * TT + t) * VOC + nb * 128 + n0l];
        dst[0] = make_float4(v[0], v[1], v[2], v[3]);
        dst[1] = make_float4(v[4], v[5], v[6], v[7]);
        atomicMax(&s_amax[m], best);
    }
    __syncthreads();
    if (tid < 64) atomicMax(&g_amax[t][tid], s_amax[tid]);
}

// ---------------- final h/c tail (only if output is concatenated tuple) -------
__global__ void final_kernel(float* __restrict__ out, int out_size) {
    int idx = blockIdx.x * blockDim.x + threadIdx.x;
    const size_t base = (size_t)BB * TT * VOC;
    if ((size_t)out_size >= base + 2ull * BB * HIDD) {
        if (idx < BB * HIDD) {
            out[base + idx]             = g_hbuf[0][idx];   // h after 64 steps is buf 0
            out[base + BB * HIDD + idx] = g_cbuf[idx];
        }
    }
}

// ---------------- launch ----------------
extern "C" void kernel_launch(void* const* d_in, const int* in_sizes, int n_in,
                              void* d_out, int out_size) {
    const float* encoder_h = (const float*)d_in[0];
    const float* encoder_c = (const float*)d_in[1];
    const void*  target    = d_in[2];
    const int*   tf_mask   = (const int*)d_in[3];
    const float* embedding = (const float*)d_in[4];
    const float* w_ih      = (const float*)d_in[5];
    const float* w_hh      = (const float*)d_in[6];
    const float* b_ih      = (const float*)d_in[7];
    const float* b_hh      = (const float*)d_in[8];
    const float* fc_w      = (const float*)d_in[9];
    const float* fc_b      = (const float*)d_in[10];
    float* out = (float*)d_out;

    cudaFuncSetAttribute(gates_kernel,
                         cudaFuncAttributeMaxDynamicSharedMemorySize, G_SMEM_BYTES);

    init_kernel<<<128, 256>>>(encoder_h, encoder_c, (const int*)target);
    for (int t = 0; t < TT; ++t) {
        gates_kernel<<<128, 256, G_SMEM_BYTES>>>(t, (const long long*)target,
                                                 (const int*)target, tf_mask, embedding,
                                                 w_ih, w_hh, b_ih, b_hh);
        fc_kernel<<<250, 256>>>(t, fc_w, fc_b, out);
    }
    final_kernel<<<128, 256>>>(out, out_size);
}